// round 12
// baseline (speedup 1.0000x reference)
#include <cuda_runtime.h>
#include <cuda_bf16.h>
#include <cstdint>

// ---------------- problem constants ----------------
#define HN     32
#define DH     128
#define NSEQ   4096
#define HIDDIM 2048
#define INNERD 4096
#define BLK    256
#define NBK    16

typedef unsigned long long u64;

// ---------------- scratch (device globals; no allocation allowed) ----------------
__device__ float g_q[HN][NSEQ][DH];
__device__ float g_k[HN][NSEQ][DH];
__device__ float g_v[HN][NSEQ][DH];
__device__ float g_kvb [HN][NBK][DH][DH];
__device__ float g_kvin[HN][NBK][DH][DH];
__device__ float g_S[HN * NBK][BLK][BLK];
__device__ float g_hidden [NSEQ][INNERD];
__device__ float g_gate   [NSEQ][INNERD];
__device__ float g_hidden2[NSEQ][INNERD];

// bf16 hi/lo split operand buffers (tiled + pre-swizzled 16KB tile images)
__device__ __align__(1024) __nv_bfloat16 g_Ah1[NSEQ * HIDDIM];
__device__ __align__(1024) __nv_bfloat16 g_Al1[NSEQ * HIDDIM];
__device__ __align__(1024) __nv_bfloat16 g_Ah2[NSEQ * INNERD];
__device__ __align__(1024) __nv_bfloat16 g_Al2[NSEQ * INNERD];
__device__ __align__(1024) __nv_bfloat16 g_Bqh[HIDDIM * 3 * INNERD];
__device__ __align__(1024) __nv_bfloat16 g_Bql[HIDDIM * 3 * INNERD];
__device__ __align__(1024) __nv_bfloat16 g_Bgh[HIDDIM * INNERD];
__device__ __align__(1024) __nv_bfloat16 g_Bgl[HIDDIM * INNERD];
__device__ __align__(1024) __nv_bfloat16 g_Boh[INNERD * HIDDIM];
__device__ __align__(1024) __nv_bfloat16 g_Bol[INNERD * HIDDIM];

// ---------------- small helpers ----------------
#define SWZ(o) ((o) ^ (((o) >> 3) & 0x70))

__device__ __forceinline__ uint32_t smem_u32(const void* p) {
    uint32_t a;
    asm("{ .reg .u64 t; cvta.to.shared.u64 t, %1; cvt.u32.u64 %0, t; }" : "=r"(a) : "l"(p));
    return a;
}

__device__ __forceinline__ u64 pack2(float lo, float hi) {
    u64 r; asm("mov.b64 %0, {%1, %2};" : "=l"(r) : "f"(lo), "f"(hi)); return r;
}
__device__ __forceinline__ void fma2(u64& c, u64 a, u64 b) {
    asm("fma.rn.f32x2 %0, %1, %2, %0;" : "+l"(c) : "l"(a), "l"(b));
}
__device__ __forceinline__ float2 unpack2(u64 v) {
    float lo, hi; asm("mov.b64 {%0, %1}, %2;" : "=f"(lo), "=f"(hi) : "l"(v));
    return make_float2(lo, hi);
}

__device__ __forceinline__ float slope_of(int h) {
    return exp2f(-0.25f * (float)(h + 1)) * 1.00001f;
}

// ---------------- mbarrier / bulk-copy primitives (sm_90 baseline) ----------------
__device__ __forceinline__ void mbar_init(uint32_t mbar, uint32_t cnt) {
    asm volatile("mbarrier.init.shared.b64 [%0], %1;" :: "r"(mbar), "r"(cnt) : "memory");
}
__device__ __forceinline__ void mbar_expect_tx(uint32_t mbar, uint32_t bytes) {
    asm volatile("mbarrier.arrive.expect_tx.shared.b64 _, [%0], %1;" :: "r"(mbar), "r"(bytes) : "memory");
}
__device__ __forceinline__ void mbar_wait(uint32_t mbar, uint32_t parity) {
    asm volatile(
        "{\n\t.reg .pred P;\n\t"
        "W_%=:\n\t"
        "mbarrier.try_wait.parity.acquire.cta.shared::cta.b64 P, [%0], %1, 0x989680;\n\t"
        "@!P bra W_%=;\n\t}"
        :: "r"(mbar), "r"(parity) : "memory");
}
__device__ __forceinline__ void bulk_g2s(uint32_t dst, const void* src, uint32_t bytes, uint32_t mbar) {
    asm volatile(
        "cp.async.bulk.shared::cluster.global.mbarrier::complete_tx::bytes [%0], [%1], %2, [%3];"
        :: "r"(dst), "l"(src), "r"(bytes), "r"(mbar) : "memory");
}

// ---------------- HMMA primitives ----------------
__device__ __forceinline__ void ldsm4(uint32_t (&r)[4], uint32_t addr) {
    asm volatile("ldmatrix.sync.aligned.m8n8.x4.shared.b16 {%0,%1,%2,%3}, [%4];"
                 : "=r"(r[0]), "=r"(r[1]), "=r"(r[2]), "=r"(r[3]) : "r"(addr));
}
__device__ __forceinline__ void mma_bf16(float (&c)[4], const uint32_t (&a)[4],
                                         uint32_t b0, uint32_t b1) {
    asm volatile("mma.sync.aligned.m16n8k16.row.col.f32.bf16.bf16.f32 "
                 "{%0,%1,%2,%3}, {%4,%5,%6,%7}, {%8,%9}, {%0,%1,%2,%3};"
                 : "+f"(c[0]), "+f"(c[1]), "+f"(c[2]), "+f"(c[3])
                 : "r"(a[0]), "r"(a[1]), "r"(a[2]), "r"(a[3]), "r"(b0), "r"(b1));
}

// ---------------- conversion: fp32 -> swizzled bf16 hi/lo tiles ----------------
// A (row-major [M][K]): tile (mt, chunk) = 128 rows x 64 k, tile idx mt*Kc+chunk
__global__ void conv_a_kernel(const float* __restrict__ X,
                              __nv_bfloat16* __restrict__ Gh,
                              __nv_bfloat16* __restrict__ Gl, int K) {
    const int chunk = blockIdx.x, mt = blockIdx.y, Kc = gridDim.x;
    __shared__ __nv_bfloat16 sh[8192], sl[8192];
    const int tid = threadIdx.x;
    for (int idx = tid; idx < 8192; idx += 256) {
        int r = idx >> 6, c = idx & 63;
        float v = X[(size_t)(mt * 128 + r) * K + chunk * 64 + c];
        __nv_bfloat16 h = __float2bfloat16(v);
        __nv_bfloat16 l = __float2bfloat16(v - __bfloat162float(h));
        uint32_t sw = SWZ((uint32_t)(r * 128 + c * 2));
        *(__nv_bfloat16*)((char*)sh + sw) = h;
        *(__nv_bfloat16*)((char*)sl + sw) = l;
    }
    __syncthreads();
    size_t base = ((size_t)mt * Kc + chunk) * 8192;
    uint4* gh = (uint4*)(Gh + base);
    uint4* gl = (uint4*)(Gl + base);
    for (int idx = tid; idx < 1024; idx += 256) {
        gh[idx] = ((const uint4*)sh)[idx];
        gl[idx] = ((const uint4*)sl)[idx];
    }
}

// W (row-major [K][N]) -> transposed tiles: tile (nt, chunk) = 128 n-rows x 64 k
__global__ void conv_w_kernel(const float* __restrict__ W,
                              __nv_bfloat16* __restrict__ Gh,
                              __nv_bfloat16* __restrict__ Gl, int N) {
    const int chunk = blockIdx.x, nt = blockIdx.y, Kc = gridDim.x;
    __shared__ __nv_bfloat16 sh[8192], sl[8192];
    const int tid = threadIdx.x;
    for (int idx = tid; idx < 8192; idx += 256) {
        int r = idx & 127, c = idx >> 7;
        float v = W[(size_t)(chunk * 64 + c) * N + nt * 128 + r];
        __nv_bfloat16 h = __float2bfloat16(v);
        __nv_bfloat16 l = __float2bfloat16(v - __bfloat162float(h));
        uint32_t sw = SWZ((uint32_t)(r * 128 + c * 2));
        *(__nv_bfloat16*)((char*)sh + sw) = h;
        *(__nv_bfloat16*)((char*)sl + sw) = l;
    }
    __syncthreads();
    size_t base = ((size_t)nt * Kc + chunk) * 8192;
    uint4* gh = (uint4*)(Gh + base);
    uint4* gl = (uint4*)(Gl + base);
    for (int idx = tid; idx < 1024; idx += 256) {
        gh[idx] = ((const uint4*)sh)[idx];
        gl[idx] = ((const uint4*)sl)[idx];
    }
}

// ---------------- HMMA GEMM: CTA tile 128m x 256n, bf16x3 split ----------------
// smem: [0..15]=pad, [16..31]=full mbar[2], [1024 + s*98304] = stage s:
//   Ah 16K | Al 16K | Bh0 16K | Bh1 16K | Bl0 16K | Bl1 16K
#define ST_BYTES 98304
#define SMEM_GEMM (1024 + 2 * ST_BYTES)

__device__ __forceinline__ void gemm_fill(uint32_t sb, int s, int c, int Kc, int mt, int nt,
                                          const __nv_bfloat16* Ah, const __nv_bfloat16* Al,
                                          const __nv_bfloat16* Bh, const __nv_bfloat16* Bl) {
    uint32_t full = sb + 16 + s * 8;
    mbar_expect_tx(full, 98304u);
    uint32_t dst = sb + 1024 + s * ST_BYTES;
    size_t at = ((size_t)mt * Kc + c) * 8192;
    size_t b0 = ((size_t)(2 * nt) * Kc + c) * 8192;
    size_t b1 = ((size_t)(2 * nt + 1) * Kc + c) * 8192;
    bulk_g2s(dst,          Ah + at, 16384u, full);
    bulk_g2s(dst + 16384u, Al + at, 16384u, full);
    bulk_g2s(dst + 32768u, Bh + b0, 16384u, full);
    bulk_g2s(dst + 49152u, Bh + b1, 16384u, full);
    bulk_g2s(dst + 65536u, Bl + b0, 16384u, full);
    bulk_g2s(dst + 81920u, Bl + b1, 16384u, full);
}

template <int EPI>  // 0: plain->C, 1: sigmoid->g_gate, 2: silu->q/k/v scatter
__global__ void __launch_bounds__(256, 1) gemm_mma_kernel(
    const __nv_bfloat16* __restrict__ Ah, const __nv_bfloat16* __restrict__ Al,
    const __nv_bfloat16* __restrict__ Bh, const __nv_bfloat16* __restrict__ Bl,
    float* __restrict__ C, int Kc, int N)
{
    extern __shared__ char smem[];
    const uint32_t sb = smem_u32(smem);
    const int tid = threadIdx.x;
    const int wid = tid >> 5, lid = tid & 31;
    const int mt = blockIdx.x, nt = blockIdx.y;
    const int warp_m = wid >> 1;          // 0..3 -> 32 rows each
    const int warp_n = wid & 1;           // 0..1 -> 128 cols each (one 16KB B tile)

    if (tid == 0) {
        mbar_init(sb + 16, 1);
        mbar_init(sb + 24, 1);
        asm volatile("fence.proxy.async.shared::cta;" ::: "memory");
        gemm_fill(sb, 0, 0, Kc, mt, nt, Ah, Al, Bh, Bl);
        if (Kc > 1) gemm_fill(sb, 1, 1, Kc, mt, nt, Ah, Al, Bh, Bl);
    }
    __syncthreads();

    // per-lane ldmatrix address components
    const int a_row  = lid & 15;
    const int a_koff = (lid >> 4) << 4;                    // bytes
    const int b_row  = (lid & 7) + ((lid >> 4) << 3);
    const int b_koff = ((lid >> 3) & 1) << 4;              // bytes

    float acc[2][16][4];
#pragma unroll
    for (int mi = 0; mi < 2; mi++)
#pragma unroll
        for (int ni = 0; ni < 16; ni++)
#pragma unroll
            for (int j = 0; j < 4; j++) acc[mi][ni][j] = 0.f;

    for (int c = 0; c < Kc; c++) {
        const int s = c & 1;
        mbar_wait(sb + 16 + s * 8, (c >> 1) & 1);
        const uint32_t st = sb + 1024 + s * ST_BYTES;
        const uint32_t sAh = st;
        const uint32_t sAl = st + 16384u;
        const uint32_t sBh = st + 32768u + warp_n * 16384u;
        const uint32_t sBl = st + 65536u + warp_n * 16384u;

#pragma unroll
        for (int k16 = 0; k16 < 4; k16++) {
            const int kb = k16 * 32;   // byte offset of this k16 within tile row
            uint32_t fah[2][4], fal[2][4];
#pragma unroll
            for (int mi = 0; mi < 2; mi++) {
                uint32_t off = SWZ((uint32_t)((warp_m * 32 + mi * 16 + a_row) * 128 + kb + a_koff));
                ldsm4(fah[mi], sAh + off);
                ldsm4(fal[mi], sAl + off);
            }
#pragma unroll
            for (int g = 0; g < 8; g++) {   // 8 groups of n16 (2 ntiles each)
                uint32_t off = SWZ((uint32_t)((g * 16 + b_row) * 128 + kb + b_koff));
                uint32_t fbh[4], fbl[4];
                ldsm4(fbh, sBh + off);
                ldsm4(fbl, sBl + off);
#pragma unroll
                for (int mi = 0; mi < 2; mi++) {
                    mma_bf16(acc[mi][2 * g],     fah[mi], fbh[0], fbh[1]);
                    mma_bf16(acc[mi][2 * g],     fah[mi], fbl[0], fbl[1]);
                    mma_bf16(acc[mi][2 * g],     fal[mi], fbh[0], fbh[1]);
                    mma_bf16(acc[mi][2 * g + 1], fah[mi], fbh[2], fbh[3]);
                    mma_bf16(acc[mi][2 * g + 1], fah[mi], fbl[2], fbl[3]);
                    mma_bf16(acc[mi][2 * g + 1], fal[mi], fbh[2], fbh[3]);
                }
            }
        }
        __syncthreads();                       // all warps done reading stage s
        if (tid == 0 && c + 2 < Kc)
            gemm_fill(sb, s, c + 2, Kc, mt, nt, Ah, Al, Bh, Bl);
    }

    // ---------------- epilogue ----------------
    const int m_base = mt * 128 + warp_m * 32;
    const int n_base = nt * 256 + warp_n * 128;
    const int r0 = lid >> 2;
    const int cpair = (lid & 3) * 2;
#pragma unroll
    for (int mi = 0; mi < 2; mi++) {
#pragma unroll
        for (int ni = 0; ni < 16; ni++) {
            float v0 = acc[mi][ni][0], v1 = acc[mi][ni][1];
            float v2 = acc[mi][ni][2], v3 = acc[mi][ni][3];
            const int row0 = m_base + mi * 16 + r0;
            const int row1 = row0 + 8;
            const int col  = n_base + ni * 8 + cpair;
            if (EPI == 0) {
                *(float2*)(C + (size_t)row0 * N + col) = make_float2(v0, v1);
                *(float2*)(C + (size_t)row1 * N + col) = make_float2(v2, v3);
            } else if (EPI == 1) {
                v0 = 1.f / (1.f + __expf(-v0)); v1 = 1.f / (1.f + __expf(-v1));
                v2 = 1.f / (1.f + __expf(-v2)); v3 = 1.f / (1.f + __expf(-v3));
                *(float2*)&g_gate[row0][col] = make_float2(v0, v1);
                *(float2*)&g_gate[row1][col] = make_float2(v2, v3);
            } else {
                v0 = v0 / (1.f + __expf(-v0)); v1 = v1 / (1.f + __expf(-v1));
                v2 = v2 / (1.f + __expf(-v2)); v3 = v3 / (1.f + __expf(-v3));
                const int h = col / 384;
                const int rc = col - h * 384;
                const int part = rc >> 7, d = rc & 127;
                float* base = (part == 0) ? &g_q[h][0][0]
                            : (part == 1) ? &g_k[h][0][0]
                                          : &g_v[h][0][0];
                *(float2*)(base + (size_t)row0 * 128 + d) = make_float2(v0, v1);
                *(float2*)(base + (size_t)row1 * 128 + d) = make_float2(v2, v3);
            }
        }
    }
}

// ---------------- FFMA2 microtile (used by attention kernels) ----------------
__device__ __forceinline__ void mm_tile16(const float* __restrict__ As,
                                          const float* __restrict__ Bs,
                                          int tx, int ty, u64 c2[8][4]) {
#pragma unroll
    for (int kk = 0; kk < 16; kk++) {
        const float* ap = As + kk * 128;
        const float* bp = Bs + kk * 128;
        float4 a0 = *(const float4*)(ap + ty * 4);
        float4 a1 = *(const float4*)(ap + ty * 4 + 64);
        ulonglong2 bA = *(const ulonglong2*)(bp + tx * 4);
        ulonglong2 bB = *(const ulonglong2*)(bp + tx * 4 + 64);
        float av[8] = {a0.x, a0.y, a0.z, a0.w, a1.x, a1.y, a1.z, a1.w};
        u64 bv[4] = {bA.x, bA.y, bB.x, bB.y};
#pragma unroll
        for (int i = 0; i < 8; i++) {
            u64 ai = pack2(av[i], av[i]);
#pragma unroll
            for (int p = 0; p < 4; p++) fma2(c2[i][p], ai, bv[p]);
        }
    }
}

#define ZERO_ACC(c2)                          \
    do {                                      \
        _Pragma("unroll")                     \
        for (int i = 0; i < 8; i++)           \
            _Pragma("unroll")                 \
            for (int p = 0; p < 4; p++)       \
                (c2)[i][p] = 0ull;            \
    } while (0)

// ---------------- attention phase A: per-block KV contributions ----------------
__global__ void __launch_bounds__(256, 2) kvblock_kernel() {
    const int b = blockIdx.x, h = blockIdx.y;
    const float s = slope_of(h);
    __shared__ float ks[2][16][128];
    __shared__ float vs[2][16][128];
    const int tid = threadIdx.x;
    const int tx = tid & 15, ty = tid >> 4;
    const int row = tid >> 5, c4 = tid & 31;
    const float* kp = &g_k[h][b * BLK][0];
    const float* vp = &g_v[h][b * BLK][0];

    u64 c2[8][4];
    ZERO_ACC(c2);

#pragma unroll
    for (int it = 0; it < 2; ++it) {
        int r = row + it * 8;
        float kd = __expf(-s * (float)(255 - r));
        float4 kv4 = *(const float4*)(kp + r * 128 + c4 * 4);
        kv4.x *= kd; kv4.y *= kd; kv4.z *= kd; kv4.w *= kd;
        *(float4*)&ks[0][r][c4 * 4] = kv4;
        *(float4*)&vs[0][r][c4 * 4] = *(const float4*)(vp + r * 128 + c4 * 4);
    }
    __syncthreads();

    for (int t = 0; t < 16; t++) {
        const int cur = t & 1;
        float4 rk[2], rv[2];
        if (t + 1 < 16) {
            int base = (t + 1) * 16;
#pragma unroll
            for (int it = 0; it < 2; ++it) {
                int gr = base + row + it * 8;
                float kd = __expf(-s * (float)(255 - gr));
                rk[it] = *(const float4*)(kp + gr * 128 + c4 * 4);
                rk[it].x *= kd; rk[it].y *= kd; rk[it].z *= kd; rk[it].w *= kd;
                rv[it] = *(const float4*)(vp + gr * 128 + c4 * 4);
            }
        }
        mm_tile16(&ks[cur][0][0], &vs[cur][0][0], tx, ty, c2);
        if (t + 1 < 16) {
            const int nx = cur ^ 1;
#pragma unroll
            for (int it = 0; it < 2; ++it) {
                *(float4*)&ks[nx][row + it * 8][c4 * 4] = rk[it];
                *(float4*)&vs[nx][row + it * 8][c4 * 4] = rv[it];
            }
        }
        __syncthreads();
    }

#pragma unroll
    for (int i = 0; i < 8; i++) {
        int drow = (i < 4) ? (ty * 4 + i) : (64 + ty * 4 + i - 4);
#pragma unroll
        for (int hf = 0; hf < 2; ++hf) {
            float2 f0 = unpack2(c2[i][hf * 2 + 0]);
            float2 f1 = unpack2(c2[i][hf * 2 + 1]);
            *(float4*)&g_kvb[h][b][drow][tx * 4 + hf * 64] =
                make_float4(f0.x, f0.y, f1.x, f1.y);
        }
    }
}

// ---------------- attention phase B: KV prefix scan across blocks ----------------
__global__ void scan_kernel(const float* __restrict__ kv0) {
    int gid = blockIdx.x * 256 + threadIdx.x;
    int h = gid >> 14, de = gid & 16383;
    float dec = __expf(-slope_of(h) * 256.f);
    float kv = kv0[gid];
#pragma unroll
    for (int b = 0; b < NBK; b++) {
        (&g_kvin[h][b][0][0])[de] = kv;
        kv = dec * kv + (&g_kvb[h][b][0][0])[de];
    }
}

// ---------------- attention phase C1: S = decay-masked q @ k^T ----------------
__global__ void __launch_bounds__(256, 2) qk_kernel() {
    const int bz = blockIdx.z;
    const int h = bz >> 4, b = bz & 15;
    const int jt0 = blockIdx.x, it0 = blockIdx.y;
    const int tid = threadIdx.x, tx = tid & 15, ty = tid >> 4;
    const float s = slope_of(h);

    u64 c2[8][4];
    ZERO_ACC(c2);

    __shared__ float As[2][16][128];
    __shared__ float Bs[2][16][128];

    if (it0 >= jt0) {
        const int arow = tid >> 2, ac4 = tid & 3;
        const float* qp = &g_q[h][b * BLK + it0 * 128][0];
        const float* kp = &g_k[h][b * BLK + jt0 * 128][0];
#pragma unroll
        for (int it = 0; it < 2; ++it) {
            int r = arow + it * 64, kk = ac4 * 4;
            float4 va = *(const float4*)(qp + r * 128 + ac4 * 4);
            As[0][kk + 0][r] = va.x; As[0][kk + 1][r] = va.y;
            As[0][kk + 2][r] = va.z; As[0][kk + 3][r] = va.w;
            float4 vb = *(const float4*)(kp + r * 128 + ac4 * 4);
            Bs[0][kk + 0][r] = vb.x; Bs[0][kk + 1][r] = vb.y;
            Bs[0][kk + 2][r] = vb.z; Bs[0][kk + 3][r] = vb.w;
        }
        __syncthreads();
        for (int t = 0; t < 8; t++) {
            const int cur = t & 1;
            float4 ra[2], rb[2];
            if (t + 1 < 8) {
                int k0 = (t + 1) * 16;
#pragma unroll
                for (int it = 0; it < 2; ++it) {
                    int r = arow + it * 64;
                    ra[it] = *(const float4*)(qp + r * 128 + k0 + ac4 * 4);
                    rb[it] = *(const float4*)(kp + r * 128 + k0 + ac4 * 4);
                }
            }
            mm_tile16(&As[cur][0][0], &Bs[cur][0][0], tx, ty, c2);
            if (t + 1 < 8) {
                const int nx = cur ^ 1;
#pragma unroll
                for (int it = 0; it < 2; ++it) {
                    int r = arow + it * 64, kk = ac4 * 4;
                    As[nx][kk + 0][r] = ra[it].x; As[nx][kk + 1][r] = ra[it].y;
                    As[nx][kk + 2][r] = ra[it].z; As[nx][kk + 3][r] = ra[it].w;
                    Bs[nx][kk + 0][r] = rb[it].x; Bs[nx][kk + 1][r] = rb[it].y;
                    Bs[nx][kk + 2][r] = rb[it].z; Bs[nx][kk + 3][r] = rb[it].w;
                }
            }
            __syncthreads();
        }
    }

    float* Sp = &g_S[bz][0][0];
#pragma unroll
    for (int i = 0; i < 8; i++) {
        int rl = (i < 4) ? (ty * 4 + i) : (64 + ty * 4 + i - 4);
        int gi = it0 * 128 + rl;
#pragma unroll
        for (int hf = 0; hf < 2; ++hf) {
            float2 f0 = unpack2(c2[i][hf * 2 + 0]);
            float2 f1 = unpack2(c2[i][hf * 2 + 1]);
            float vv[4] = {f0.x, f0.y, f1.x, f1.y};
            int j0 = jt0 * 128 + tx * 4 + hf * 64;
#pragma unroll
            for (int jj = 0; jj < 4; jj++) {
                int diff = gi - (j0 + jj);
                vv[jj] = (diff >= 0) ? vv[jj] * __expf(-s * (float)diff) : 0.f;
            }
            *(float4*)(Sp + gi * 256 + j0) = make_float4(vv[0], vv[1], vv[2], vv[3]);
        }
    }
}

// ---------------- attention phase C2: out = S @ v + (q*qdec) @ kv_in ----------------
__global__ void __launch_bounds__(256, 2) av_kernel() {
    const int it0 = blockIdx.x;
    const int bz = blockIdx.y;
    const int h = bz >> 4, b = bz & 15;
    const float s = slope_of(h);
    const int tid = threadIdx.x, tx = tid & 15, ty = tid >> 4;
    __shared__ float As[2][16][128];
    __shared__ float Bs[2][16][128];
    const int arow = tid >> 2, ac4 = tid & 3;
    const int brow = tid >> 5, bc4 = tid & 31;

    u64 c2[8][4];
    ZERO_ACC(c2);

    const float* Sp = &g_S[bz][it0 * 128][0];
    const float* vp = &g_v[h][b * BLK][0];
#pragma unroll
    for (int it = 0; it < 2; ++it) {
        int r = arow + it * 64, kk = ac4 * 4;
        float4 va = *(const float4*)(Sp + r * 256 + ac4 * 4);
        As[0][kk + 0][r] = va.x; As[0][kk + 1][r] = va.y;
        As[0][kk + 2][r] = va.z; As[0][kk + 3][r] = va.w;
        float4 vb = *(const float4*)(vp + (brow + it * 8) * 128 + bc4 * 4);
        *(float4*)&Bs[0][brow + it * 8][bc4 * 4] = vb;
    }
    __syncthreads();
    for (int t = 0; t < 16; t++) {
        const int cur = t & 1;
        float4 ra[2], rb[2];
        if (t + 1 < 16) {
            int k0 = (t + 1) * 16;
#pragma unroll
            for (int it = 0; it < 2; ++it) {
                ra[it] = *(const float4*)(Sp + (arow + it * 64) * 256 + k0 + ac4 * 4);
                rb[it] = *(const float4*)(vp + (k0 + brow + it * 8) * 128 + bc4 * 4);
            }
        }
        mm_tile16(&As[cur][0][0], &Bs[cur][0][0], tx, ty, c2);
        if (t + 1 < 16) {
            const int nx = cur ^ 1;
#pragma unroll
            for (int it = 0; it < 2; ++it) {
                int r = arow + it * 64, kk = ac4 * 4;
                As[nx][kk + 0][r] = ra[it].x; As[nx][kk + 1][r] = ra[it].y;
                As[nx][kk + 2][r] = ra[it].z; As[nx][kk + 3][r] = ra[it].w;
                *(float4*)&Bs[nx][brow + it * 8][bc4 * 4] = rb[it];
            }
        }
        __syncthreads();
    }

    const float* qp = &g_q[h][b * BLK + it0 * 128][0];
    const float* kvp = &g_kvin[h][b][0][0];
#pragma unroll
    for (int it = 0; it < 2; ++it) {
        int r = arow + it * 64, kk = ac4 * 4;
        float qd = __expf(-s * (float)(it0 * 128 + r + 1));
        float4 va = *(const float4*)(qp + r * 128 + ac4 * 4);
        As[0][kk + 0][r] = va.x * qd; As[0][kk + 1][r] = va.y * qd;
        As[0][kk + 2][r] = va.z * qd; As[0][kk + 3][r] = va.w * qd;
        float4 vb = *(const float4*)(kvp + (brow + it * 8) * 128 + bc4 * 4);
        *(float4*)&Bs[0][brow + it * 8][bc4 * 4] = vb;
    }
    __syncthreads();
    for (int t = 0; t < 8; t++) {
        const int cur = t & 1;
        float4 ra[2], rb[2];
        float qd2[2];
        if (t + 1 < 8) {
            int k0 = (t + 1) * 16;
#pragma unroll
            for (int it = 0; it < 2; ++it) {
                int r = arow + it * 64;
                qd2[it] = __expf(-s * (float)(it0 * 128 + r + 1));
                ra[it] = *(const float4*)(qp + r * 128 + k0 + ac4 * 4);
                rb[it] = *(const float4*)(kvp + (k0 + brow + it * 8) * 128 + bc4 * 4);
            }
        }
        mm_tile16(&As[cur][0][0], &Bs[cur][0][0], tx, ty, c2);
        if (t + 1 < 8) {
            const int nx = cur ^ 1;
#pragma unroll
            for (int it = 0; it < 2; ++it) {
                int r = arow + it * 64, kk = ac4 * 4;
                As[nx][kk + 0][r] = ra[it].x * qd2[it];
                As[nx][kk + 1][r] = ra[it].y * qd2[it];
                As[nx][kk + 2][r] = ra[it].z * qd2[it];
                As[nx][kk + 3][r] = ra[it].w * qd2[it];
                *(float4*)&Bs[nx][brow + it * 8][bc4 * 4] = rb[it];
            }
        }
        __syncthreads();
    }

#pragma unroll
    for (int i = 0; i < 8; i++) {
        int rl = (i < 4) ? (ty * 4 + i) : (64 + ty * 4 + i - 4);
        int mseq = b * BLK + it0 * 128 + rl;
#pragma unroll
        for (int hf = 0; hf < 2; ++hf) {
            float2 f0 = unpack2(c2[i][hf * 2 + 0]);
            float2 f1 = unpack2(c2[i][hf * 2 + 1]);
            *(float4*)&g_hidden[mseq][h * 128 + tx * 4 + hf * 64] =
                make_float4(f0.x, f0.y, f1.x, f1.y);
        }
    }
}

// ---------------- rmsnorm * norm_weight * sigmoid(gate) ----------------
__global__ void norm_kernel(const float* __restrict__ nw) {
    const int m = blockIdx.x;
    const int tid = threadIdx.x;
    const float4* hp = (const float4*)&g_hidden[m][0];
    float4 vals[4];
    float ss = 0.f;
#pragma unroll
    for (int i = 0; i < 4; i++) {
        float4 v = hp[tid + i * 256];
        vals[i] = v;
        ss += v.x * v.x + v.y * v.y + v.z * v.z + v.w * v.w;
    }
    __shared__ float red[256];
    red[tid] = ss;
    __syncthreads();
    for (int s = 128; s > 0; s >>= 1) {
        if (tid < s) red[tid] += red[tid + s];
        __syncthreads();
    }
    float inv = rsqrtf(red[0] / 4096.f + 1e-5f);
#pragma unroll
    for (int i = 0; i < 4; i++) {
        int c = (tid + i * 256) * 4;
        float4 v = vals[i];
        float4 g = *(const float4*)&g_gate[m][c];
        float4 w = *(const float4*)&nw[c];
        float4 o;
        o.x = v.x * inv * w.x * g.x;
        o.y = v.y * inv * w.y * g.y;
        o.z = v.z * inv * w.z * g.z;
        o.w = v.w * inv * w.w * g.w;
        *(float4*)&g_hidden2[m][c] = o;
    }
}

// ---------------- launch ----------------
extern "C" void kernel_launch(void* const* d_in, const int* in_sizes, int n_in,
                              void* d_out, int out_size) {
    const float* hs    = (const float*)d_in[0];
    const float* kv0   = (const float*)d_in[2];
    const float* Wqkv  = (const float*)d_in[3];
    const float* Wgate = (const float*)d_in[4];
    const float* Wout  = (const float*)d_in[5];
    const float* nw    = (const float*)d_in[6];
    float* out = (float*)d_out;

    float *hid2;
    __nv_bfloat16 *ah1, *al1, *ah2, *al2, *bqh, *bql, *bgh, *bgl, *boh, *bol;
    cudaGetSymbolAddress((void**)&hid2, g_hidden2);
    cudaGetSymbolAddress((void**)&ah1, g_Ah1);
    cudaGetSymbolAddress((void**)&al1, g_Al1);
    cudaGetSymbolAddress((void**)&ah2, g_Ah2);
    cudaGetSymbolAddress((void**)&al2, g_Al2);
    cudaGetSymbolAddress((void**)&bqh, g_Bqh);
    cudaGetSymbolAddress((void**)&bql, g_Bql);
    cudaGetSymbolAddress((void**)&bgh, g_Bgh);
    cudaGetSymbolAddress((void**)&bgl, g_Bgl);
    cudaGetSymbolAddress((void**)&boh, g_Boh);
    cudaGetSymbolAddress((void**)&bol, g_Bol);

    cudaFuncSetAttribute(gemm_mma_kernel<0>, cudaFuncAttributeMaxDynamicSharedMemorySize, SMEM_GEMM);
    cudaFuncSetAttribute(gemm_mma_kernel<1>, cudaFuncAttributeMaxDynamicSharedMemorySize, SMEM_GEMM);
    cudaFuncSetAttribute(gemm_mma_kernel<2>, cudaFuncAttributeMaxDynamicSharedMemorySize, SMEM_GEMM);

    dim3 thr(256);
    // operand conversions (fp32 -> bf16 hi/lo, tiled & pre-swizzled)
    conv_a_kernel<<<dim3(32, 32), thr>>>(hs, ah1, al1, HIDDIM);
    conv_w_kernel<<<dim3(32, 96), thr>>>(Wqkv, bqh, bql, 3 * INNERD);
    conv_w_kernel<<<dim3(32, 32), thr>>>(Wgate, bgh, bgl, INNERD);
    conv_w_kernel<<<dim3(64, 16), thr>>>(Wout, boh, bol, HIDDIM);

    // qkv = silu(hs @ W_qkv) -> scatter q/k/v    (M=4096, N=12288, K=2048)
    gemm_mma_kernel<2><<<dim3(32, 48), thr, SMEM_GEMM>>>(ah1, al1, bqh, bql, nullptr, 32, 3 * INNERD);
    // gate = sigmoid(hs @ W_gate)                (N=4096)
    gemm_mma_kernel<1><<<dim3(32, 16), thr, SMEM_GEMM>>>(ah1, al1, bgh, bgl, nullptr, 32, INNERD);

    // attention
    kvblock_kernel<<<dim3(NBK, HN), thr>>>();
    scan_kernel<<<2048, thr>>>(kv0);
    qk_kernel<<<dim3(2, 2, HN * NBK), thr>>>();
    av_kernel<<<dim3(2, HN * NBK), thr>>>();

    // rmsnorm * w * gate
    norm_kernel<<<NSEQ, thr>>>(nw);

    // out = hidden2 @ W_out                      (M=4096, N=2048, K=4096)
    conv_a_kernel<<<dim3(64, 32), thr>>>(hid2, ah2, al2, INNERD);
    gemm_mma_kernel<0><<<dim3(32, 8), thr, SMEM_GEMM>>>(ah2, al2, boh, bol, out, 64, HIDDIM);
}

// round 13
// speedup vs baseline: 1.0045x; 1.0045x over previous
#include <cuda_runtime.h>
#include <cuda_bf16.h>
#include <cstdint>

// ---------------- problem constants ----------------
#define HN     32
#define DH     128
#define NSEQ   4096
#define HIDDIM 2048
#define INNERD 4096
#define BLK    256
#define NBK    16

typedef unsigned long long u64;

// ---------------- scratch (device globals; no allocation allowed) ----------------
__device__ float g_q[HN][NSEQ][DH];
__device__ float g_k[HN][NSEQ][DH];
__device__ float g_v[HN][NSEQ][DH];
__device__ float g_kvb [HN][NBK][DH][DH];
__device__ float g_kvin[HN][NBK][DH][DH];
__device__ float g_S[HN * NBK][BLK][BLK];
__device__ float g_hidden [NSEQ][INNERD];
__device__ float g_gate   [NSEQ][INNERD];
__device__ float g_hidden2[NSEQ][INNERD];

// bf16 hi/lo split operand buffers (tiled + pre-swizzled 16KB tile images)
__device__ __align__(1024) __nv_bfloat16 g_Ah1[NSEQ * HIDDIM];
__device__ __align__(1024) __nv_bfloat16 g_Al1[NSEQ * HIDDIM];
__device__ __align__(1024) __nv_bfloat16 g_Ah2[NSEQ * INNERD];
__device__ __align__(1024) __nv_bfloat16 g_Al2[NSEQ * INNERD];
__device__ __align__(1024) __nv_bfloat16 g_Bqh[HIDDIM * 3 * INNERD];
__device__ __align__(1024) __nv_bfloat16 g_Bql[HIDDIM * 3 * INNERD];
__device__ __align__(1024) __nv_bfloat16 g_Bgh[HIDDIM * INNERD];
__device__ __align__(1024) __nv_bfloat16 g_Bgl[HIDDIM * INNERD];
__device__ __align__(1024) __nv_bfloat16 g_Boh[INNERD * HIDDIM];
__device__ __align__(1024) __nv_bfloat16 g_Bol[INNERD * HIDDIM];

// ---------------- small helpers ----------------
#define SWZ(o) ((o) ^ (((o) >> 3) & 0x70))

__device__ __forceinline__ uint32_t smem_u32(const void* p) {
    uint32_t a;
    asm("{ .reg .u64 t; cvta.to.shared.u64 t, %1; cvt.u32.u64 %0, t; }" : "=r"(a) : "l"(p));
    return a;
}

__device__ __forceinline__ u64 pack2(float lo, float hi) {
    u64 r; asm("mov.b64 %0, {%1, %2};" : "=l"(r) : "f"(lo), "f"(hi)); return r;
}
__device__ __forceinline__ void fma2(u64& c, u64 a, u64 b) {
    asm("fma.rn.f32x2 %0, %1, %2, %0;" : "+l"(c) : "l"(a), "l"(b));
}
__device__ __forceinline__ float2 unpack2(u64 v) {
    float lo, hi; asm("mov.b64 {%0, %1}, %2;" : "=f"(lo), "=f"(hi) : "l"(v));
    return make_float2(lo, hi);
}

__device__ __forceinline__ float slope_of(int h) {
    return exp2f(-0.25f * (float)(h + 1)) * 1.00001f;
}

// ---------------- mbarrier / bulk-copy primitives (sm_90 baseline) ----------------
__device__ __forceinline__ void mbar_init(uint32_t mbar, uint32_t cnt) {
    asm volatile("mbarrier.init.shared.b64 [%0], %1;" :: "r"(mbar), "r"(cnt) : "memory");
}
__device__ __forceinline__ void mbar_expect_tx(uint32_t mbar, uint32_t bytes) {
    asm volatile("mbarrier.arrive.expect_tx.shared.b64 _, [%0], %1;" :: "r"(mbar), "r"(bytes) : "memory");
}
__device__ __forceinline__ void mbar_wait(uint32_t mbar, uint32_t parity) {
    asm volatile(
        "{\n\t.reg .pred P;\n\t"
        "W_%=:\n\t"
        "mbarrier.try_wait.parity.acquire.cta.shared::cta.b64 P, [%0], %1, 0x989680;\n\t"
        "@!P bra W_%=;\n\t}"
        :: "r"(mbar), "r"(parity) : "memory");
}
__device__ __forceinline__ void bulk_g2s(uint32_t dst, const void* src, uint32_t bytes, uint32_t mbar) {
    asm volatile(
        "cp.async.bulk.shared::cluster.global.mbarrier::complete_tx::bytes [%0], [%1], %2, [%3];"
        :: "r"(dst), "l"(src), "r"(bytes), "r"(mbar) : "memory");
}

// ---------------- HMMA primitives ----------------
__device__ __forceinline__ void ldsm4(uint32_t (&r)[4], uint32_t addr) {
    asm volatile("ldmatrix.sync.aligned.m8n8.x4.shared.b16 {%0,%1,%2,%3}, [%4];"
                 : "=r"(r[0]), "=r"(r[1]), "=r"(r[2]), "=r"(r[3]) : "r"(addr));
}
__device__ __forceinline__ void mma_bf16(float (&c)[4], const uint32_t (&a)[4],
                                         uint32_t b0, uint32_t b1) {
    asm volatile("mma.sync.aligned.m16n8k16.row.col.f32.bf16.bf16.f32 "
                 "{%0,%1,%2,%3}, {%4,%5,%6,%7}, {%8,%9}, {%0,%1,%2,%3};"
                 : "+f"(c[0]), "+f"(c[1]), "+f"(c[2]), "+f"(c[3])
                 : "r"(a[0]), "r"(a[1]), "r"(a[2]), "r"(a[3]), "r"(b0), "r"(b1));
}

// ---------------- conversion: fp32 -> swizzled bf16 hi/lo tiles ----------------
// A (row-major [M][K]): tile (mt, chunk) = 128 rows x 64 k, tile idx mt*Kc+chunk
__global__ void conv_a_kernel(const float* __restrict__ X,
                              __nv_bfloat16* __restrict__ Gh,
                              __nv_bfloat16* __restrict__ Gl, int K) {
    const int chunk = blockIdx.x, mt = blockIdx.y, Kc = gridDim.x;
    __shared__ __nv_bfloat16 sh[8192], sl[8192];
    const int tid = threadIdx.x;
    for (int idx = tid; idx < 8192; idx += 256) {
        int r = idx >> 6, c = idx & 63;
        float v = X[(size_t)(mt * 128 + r) * K + chunk * 64 + c];
        __nv_bfloat16 h = __float2bfloat16(v);
        __nv_bfloat16 l = __float2bfloat16(v - __bfloat162float(h));
        uint32_t sw = SWZ((uint32_t)(r * 128 + c * 2));
        *(__nv_bfloat16*)((char*)sh + sw) = h;
        *(__nv_bfloat16*)((char*)sl + sw) = l;
    }
    __syncthreads();
    size_t base = ((size_t)mt * Kc + chunk) * 8192;
    uint4* gh = (uint4*)(Gh + base);
    uint4* gl = (uint4*)(Gl + base);
    for (int idx = tid; idx < 1024; idx += 256) {
        gh[idx] = ((const uint4*)sh)[idx];
        gl[idx] = ((const uint4*)sl)[idx];
    }
}

// W (row-major [K][N]) -> transposed tiles: tile (nt, chunk) = 128 n-rows x 64 k
__global__ void conv_w_kernel(const float* __restrict__ W,
                              __nv_bfloat16* __restrict__ Gh,
                              __nv_bfloat16* __restrict__ Gl, int N) {
    const int chunk = blockIdx.x, nt = blockIdx.y, Kc = gridDim.x;
    __shared__ __nv_bfloat16 sh[8192], sl[8192];
    const int tid = threadIdx.x;
    for (int idx = tid; idx < 8192; idx += 256) {
        int r = idx & 127, c = idx >> 7;
        float v = W[(size_t)(chunk * 64 + c) * N + nt * 128 + r];
        __nv_bfloat16 h = __float2bfloat16(v);
        __nv_bfloat16 l = __float2bfloat16(v - __bfloat162float(h));
        uint32_t sw = SWZ((uint32_t)(r * 128 + c * 2));
        *(__nv_bfloat16*)((char*)sh + sw) = h;
        *(__nv_bfloat16*)((char*)sl + sw) = l;
    }
    __syncthreads();
    size_t base = ((size_t)nt * Kc + chunk) * 8192;
    uint4* gh = (uint4*)(Gh + base);
    uint4* gl = (uint4*)(Gl + base);
    for (int idx = tid; idx < 1024; idx += 256) {
        gh[idx] = ((const uint4*)sh)[idx];
        gl[idx] = ((const uint4*)sl)[idx];
    }
}

// ---------------- HMMA GEMM: CTA tile 128m x 256n, bf16x3 split ----------------
// smem: [0..15]=pad, [16..31]=full mbar[2], [1024 + s*98304] = stage s:
//   Ah 16K | Al 16K | Bh0 16K | Bh1 16K | Bl0 16K | Bl1 16K
#define ST_BYTES 98304
#define SMEM_GEMM (1024 + 2 * ST_BYTES)

__device__ __forceinline__ void gemm_fill(uint32_t sb, int s, int c, int Kc, int mt, int nt,
                                          const __nv_bfloat16* Ah, const __nv_bfloat16* Al,
                                          const __nv_bfloat16* Bh, const __nv_bfloat16* Bl) {
    uint32_t full = sb + 16 + s * 8;
    mbar_expect_tx(full, 98304u);
    uint32_t dst = sb + 1024 + s * ST_BYTES;
    size_t at = ((size_t)mt * Kc + c) * 8192;
    size_t b0 = ((size_t)(2 * nt) * Kc + c) * 8192;
    size_t b1 = ((size_t)(2 * nt + 1) * Kc + c) * 8192;
    bulk_g2s(dst,          Ah + at, 16384u, full);
    bulk_g2s(dst + 16384u, Al + at, 16384u, full);
    bulk_g2s(dst + 32768u, Bh + b0, 16384u, full);
    bulk_g2s(dst + 49152u, Bh + b1, 16384u, full);
    bulk_g2s(dst + 65536u, Bl + b0, 16384u, full);
    bulk_g2s(dst + 81920u, Bl + b1, 16384u, full);
}

template <int EPI>  // 0: plain->C, 1: sigmoid->g_gate, 2: silu->q/k/v scatter
__global__ void __launch_bounds__(256, 1) gemm_mma_kernel(
    const __nv_bfloat16* __restrict__ Ah, const __nv_bfloat16* __restrict__ Al,
    const __nv_bfloat16* __restrict__ Bh, const __nv_bfloat16* __restrict__ Bl,
    float* __restrict__ C, int Kc, int N)
{
    extern __shared__ char smem[];
    const uint32_t sb = smem_u32(smem);
    const int tid = threadIdx.x;
    const int wid = tid >> 5, lid = tid & 31;
    const int mt = blockIdx.x, nt = blockIdx.y;
    const int warp_m = wid >> 1;          // 0..3 -> 32 rows each
    const int warp_n = wid & 1;           // 0..1 -> 128 cols each (one 16KB B tile)

    if (tid == 0) {
        mbar_init(sb + 16, 1);
        mbar_init(sb + 24, 1);
        asm volatile("fence.proxy.async.shared::cta;" ::: "memory");
        gemm_fill(sb, 0, 0, Kc, mt, nt, Ah, Al, Bh, Bl);
        if (Kc > 1) gemm_fill(sb, 1, 1, Kc, mt, nt, Ah, Al, Bh, Bl);
    }
    __syncthreads();

    // per-lane ldmatrix address components
    const int a_row  = lid & 15;
    const int a_koff = (lid >> 4) << 4;                    // bytes
    const int b_row  = (lid & 7) + ((lid >> 4) << 3);
    const int b_koff = ((lid >> 3) & 1) << 4;              // bytes

    float acc[2][16][4];
#pragma unroll
    for (int mi = 0; mi < 2; mi++)
#pragma unroll
        for (int ni = 0; ni < 16; ni++)
#pragma unroll
            for (int j = 0; j < 4; j++) acc[mi][ni][j] = 0.f;

    for (int c = 0; c < Kc; c++) {
        const int s = c & 1;
        mbar_wait(sb + 16 + s * 8, (c >> 1) & 1);
        const uint32_t st = sb + 1024 + s * ST_BYTES;
        const uint32_t sAh = st;
        const uint32_t sAl = st + 16384u;
        const uint32_t sBh = st + 32768u + warp_n * 16384u;
        const uint32_t sBl = st + 65536u + warp_n * 16384u;

#pragma unroll
        for (int k16 = 0; k16 < 4; k16++) {
            const int kb = k16 * 32;   // byte offset of this k16 within tile row
            uint32_t fah[2][4], fal[2][4];
#pragma unroll
            for (int mi = 0; mi < 2; mi++) {
                uint32_t off = SWZ((uint32_t)((warp_m * 32 + mi * 16 + a_row) * 128 + kb + a_koff));
                ldsm4(fah[mi], sAh + off);
                ldsm4(fal[mi], sAl + off);
            }
#pragma unroll
            for (int g = 0; g < 8; g++) {   // 8 groups of n16 (2 ntiles each)
                uint32_t off = SWZ((uint32_t)((g * 16 + b_row) * 128 + kb + b_koff));
                uint32_t fbh[4], fbl[4];
                ldsm4(fbh, sBh + off);
                ldsm4(fbl, sBl + off);
#pragma unroll
                for (int mi = 0; mi < 2; mi++) {
                    mma_bf16(acc[mi][2 * g],     fah[mi], fbh[0], fbh[1]);
                    mma_bf16(acc[mi][2 * g],     fah[mi], fbl[0], fbl[1]);
                    mma_bf16(acc[mi][2 * g],     fal[mi], fbh[0], fbh[1]);
                    mma_bf16(acc[mi][2 * g + 1], fah[mi], fbh[2], fbh[3]);
                    mma_bf16(acc[mi][2 * g + 1], fah[mi], fbl[2], fbl[3]);
                    mma_bf16(acc[mi][2 * g + 1], fal[mi], fbh[2], fbh[3]);
                }
            }
        }
        __syncthreads();                       // all warps done reading stage s
        if (tid == 0 && c + 2 < Kc)
            gemm_fill(sb, s, c + 2, Kc, mt, nt, Ah, Al, Bh, Bl);
    }

    // ---------------- epilogue ----------------
    const int m_base = mt * 128 + warp_m * 32;
    const int n_base = nt * 256 + warp_n * 128;
    const int r0 = lid >> 2;
    const int cpair = (lid & 3) * 2;
#pragma unroll
    for (int mi = 0; mi < 2; mi++) {
#pragma unroll
        for (int ni = 0; ni < 16; ni++) {
            float v0 = acc[mi][ni][0], v1 = acc[mi][ni][1];
            float v2 = acc[mi][ni][2], v3 = acc[mi][ni][3];
            const int row0 = m_base + mi * 16 + r0;
            const int row1 = row0 + 8;
            const int col  = n_base + ni * 8 + cpair;
            if (EPI == 0) {
                *(float2*)(C + (size_t)row0 * N + col) = make_float2(v0, v1);
                *(float2*)(C + (size_t)row1 * N + col) = make_float2(v2, v3);
            } else if (EPI == 1) {
                v0 = 1.f / (1.f + __expf(-v0)); v1 = 1.f / (1.f + __expf(-v1));
                v2 = 1.f / (1.f + __expf(-v2)); v3 = 1.f / (1.f + __expf(-v3));
                *(float2*)&g_gate[row0][col] = make_float2(v0, v1);
                *(float2*)&g_gate[row1][col] = make_float2(v2, v3);
            } else {
                v0 = v0 / (1.f + __expf(-v0)); v1 = v1 / (1.f + __expf(-v1));
                v2 = v2 / (1.f + __expf(-v2)); v3 = v3 / (1.f + __expf(-v3));
                const int h = col / 384;
                const int rc = col - h * 384;
                const int part = rc >> 7, d = rc & 127;
                float* base = (part == 0) ? &g_q[h][0][0]
                            : (part == 1) ? &g_k[h][0][0]
                                          : &g_v[h][0][0];
                *(float2*)(base + (size_t)row0 * 128 + d) = make_float2(v0, v1);
                *(float2*)(base + (size_t)row1 * 128 + d) = make_float2(v2, v3);
            }
        }
    }
}

// ---------------- FFMA2 microtile (used by attention kernels) ----------------
__device__ __forceinline__ void mm_tile16(const float* __restrict__ As,
                                          const float* __restrict__ Bs,
                                          int tx, int ty, u64 c2[8][4]) {
#pragma unroll
    for (int kk = 0; kk < 16; kk++) {
        const float* ap = As + kk * 128;
        const float* bp = Bs + kk * 128;
        float4 a0 = *(const float4*)(ap + ty * 4);
        float4 a1 = *(const float4*)(ap + ty * 4 + 64);
        ulonglong2 bA = *(const ulonglong2*)(bp + tx * 4);
        ulonglong2 bB = *(const ulonglong2*)(bp + tx * 4 + 64);
        float av[8] = {a0.x, a0.y, a0.z, a0.w, a1.x, a1.y, a1.z, a1.w};
        u64 bv[4] = {bA.x, bA.y, bB.x, bB.y};
#pragma unroll
        for (int i = 0; i < 8; i++) {
            u64 ai = pack2(av[i], av[i]);
#pragma unroll
            for (int p = 0; p < 4; p++) fma2(c2[i][p], ai, bv[p]);
        }
    }
}

#define ZERO_ACC(c2)                          \
    do {                                      \
        _Pragma("unroll")                     \
        for (int i = 0; i < 8; i++)           \
            _Pragma("unroll")                 \
            for (int p = 0; p < 4; p++)       \
                (c2)[i][p] = 0ull;            \
    } while (0)

// ---------------- attention phase A: per-block KV contributions ----------------
__global__ void __launch_bounds__(256, 2) kvblock_kernel() {
    const int b = blockIdx.x, h = blockIdx.y;
    const float s = slope_of(h);
    __shared__ float ks[2][16][128];
    __shared__ float vs[2][16][128];
    const int tid = threadIdx.x;
    const int tx = tid & 15, ty = tid >> 4;
    const int row = tid >> 5, c4 = tid & 31;
    const float* kp = &g_k[h][b * BLK][0];
    const float* vp = &g_v[h][b * BLK][0];

    u64 c2[8][4];
    ZERO_ACC(c2);

#pragma unroll
    for (int it = 0; it < 2; ++it) {
        int r = row + it * 8;
        float kd = __expf(-s * (float)(255 - r));
        float4 kv4 = *(const float4*)(kp + r * 128 + c4 * 4);
        kv4.x *= kd; kv4.y *= kd; kv4.z *= kd; kv4.w *= kd;
        *(float4*)&ks[0][r][c4 * 4] = kv4;
        *(float4*)&vs[0][r][c4 * 4] = *(const float4*)(vp + r * 128 + c4 * 4);
    }
    __syncthreads();

    for (int t = 0; t < 16; t++) {
        const int cur = t & 1;
        float4 rk[2], rv[2];
        if (t + 1 < 16) {
            int base = (t + 1) * 16;
#pragma unroll
            for (int it = 0; it < 2; ++it) {
                int gr = base + row + it * 8;
                float kd = __expf(-s * (float)(255 - gr));
                rk[it] = *(const float4*)(kp + gr * 128 + c4 * 4);
                rk[it].x *= kd; rk[it].y *= kd; rk[it].z *= kd; rk[it].w *= kd;
                rv[it] = *(const float4*)(vp + gr * 128 + c4 * 4);
            }
        }
        mm_tile16(&ks[cur][0][0], &vs[cur][0][0], tx, ty, c2);
        if (t + 1 < 16) {
            const int nx = cur ^ 1;
#pragma unroll
            for (int it = 0; it < 2; ++it) {
                *(float4*)&ks[nx][row + it * 8][c4 * 4] = rk[it];
                *(float4*)&vs[nx][row + it * 8][c4 * 4] = rv[it];
            }
        }
        __syncthreads();
    }

#pragma unroll
    for (int i = 0; i < 8; i++) {
        int drow = (i < 4) ? (ty * 4 + i) : (64 + ty * 4 + i - 4);
#pragma unroll
        for (int hf = 0; hf < 2; ++hf) {
            float2 f0 = unpack2(c2[i][hf * 2 + 0]);
            float2 f1 = unpack2(c2[i][hf * 2 + 1]);
            *(float4*)&g_kvb[h][b][drow][tx * 4 + hf * 64] =
                make_float4(f0.x, f0.y, f1.x, f1.y);
        }
    }
}

// ---------------- attention phase B: KV prefix scan across blocks ----------------
__global__ void scan_kernel(const float* __restrict__ kv0) {
    int gid = blockIdx.x * 256 + threadIdx.x;
    int h = gid >> 14, de = gid & 16383;
    float dec = __expf(-slope_of(h) * 256.f);
    float kv = kv0[gid];
#pragma unroll
    for (int b = 0; b < NBK; b++) {
        (&g_kvin[h][b][0][0])[de] = kv;
        kv = dec * kv + (&g_kvb[h][b][0][0])[de];
    }
}

// ---------------- attention phase C1: S = decay-masked q @ k^T ----------------
__global__ void __launch_bounds__(256, 2) qk_kernel() {
    const int bz = blockIdx.z;
    const int h = bz >> 4, b = bz & 15;
    const int jt0 = blockIdx.x, it0 = blockIdx.y;
    const int tid = threadIdx.x, tx = tid & 15, ty = tid >> 4;
    const float s = slope_of(h);

    u64 c2[8][4];
    ZERO_ACC(c2);

    __shared__ float As[2][16][128];
    __shared__ float Bs[2][16][128];

    if (it0 >= jt0) {
        const int arow = tid >> 2, ac4 = tid & 3;
        const float* qp = &g_q[h][b * BLK + it0 * 128][0];
        const float* kp = &g_k[h][b * BLK + jt0 * 128][0];
#pragma unroll
        for (int it = 0; it < 2; ++it) {
            int r = arow + it * 64, kk = ac4 * 4;
            float4 va = *(const float4*)(qp + r * 128 + ac4 * 4);
            As[0][kk + 0][r] = va.x; As[0][kk + 1][r] = va.y;
            As[0][kk + 2][r] = va.z; As[0][kk + 3][r] = va.w;
            float4 vb = *(const float4*)(kp + r * 128 + ac4 * 4);
            Bs[0][kk + 0][r] = vb.x; Bs[0][kk + 1][r] = vb.y;
            Bs[0][kk + 2][r] = vb.z; Bs[0][kk + 3][r] = vb.w;
        }
        __syncthreads();
        for (int t = 0; t < 8; t++) {
            const int cur = t & 1;
            float4 ra[2], rb[2];
            if (t + 1 < 8) {
                int k0 = (t + 1) * 16;
#pragma unroll
                for (int it = 0; it < 2; ++it) {
                    int r = arow + it * 64;
                    ra[it] = *(const float4*)(qp + r * 128 + k0 + ac4 * 4);
                    rb[it] = *(const float4*)(kp + r * 128 + k0 + ac4 * 4);
                }
            }
            mm_tile16(&As[cur][0][0], &Bs[cur][0][0], tx, ty, c2);
            if (t + 1 < 8) {
                const int nx = cur ^ 1;
#pragma unroll
                for (int it = 0; it < 2; ++it) {
                    int r = arow + it * 64, kk = ac4 * 4;
                    As[nx][kk + 0][r] = ra[it].x; As[nx][kk + 1][r] = ra[it].y;
                    As[nx][kk + 2][r] = ra[it].z; As[nx][kk + 3][r] = ra[it].w;
                    Bs[nx][kk + 0][r] = rb[it].x; Bs[nx][kk + 1][r] = rb[it].y;
                    Bs[nx][kk + 2][r] = rb[it].z; Bs[nx][kk + 3][r] = rb[it].w;
                }
            }
            __syncthreads();
        }
    }

    float* Sp = &g_S[bz][0][0];
#pragma unroll
    for (int i = 0; i < 8; i++) {
        int rl = (i < 4) ? (ty * 4 + i) : (64 + ty * 4 + i - 4);
        int gi = it0 * 128 + rl;
#pragma unroll
        for (int hf = 0; hf < 2; ++hf) {
            float2 f0 = unpack2(c2[i][hf * 2 + 0]);
            float2 f1 = unpack2(c2[i][hf * 2 + 1]);
            float vv[4] = {f0.x, f0.y, f1.x, f1.y};
            int j0 = jt0 * 128 + tx * 4 + hf * 64;
#pragma unroll
            for (int jj = 0; jj < 4; jj++) {
                int diff = gi - (j0 + jj);
                vv[jj] = (diff >= 0) ? vv[jj] * __expf(-s * (float)diff) : 0.f;
            }
            *(float4*)(Sp + gi * 256 + j0) = make_float4(vv[0], vv[1], vv[2], vv[3]);
        }
    }
}

// ---------------- attention phase C2: out = S @ v + (q*qdec) @ kv_in ----------------
__global__ void __launch_bounds__(256, 2) av_kernel() {
    const int it0 = blockIdx.x;
    const int bz = blockIdx.y;
    const int h = bz >> 4, b = bz & 15;
    const float s = slope_of(h);
    const int tid = threadIdx.x, tx = tid & 15, ty = tid >> 4;
    __shared__ float As[2][16][128];
    __shared__ float Bs[2][16][128];
    const int arow = tid >> 2, ac4 = tid & 3;
    const int brow = tid >> 5, bc4 = tid & 31;

    u64 c2[8][4];
    ZERO_ACC(c2);

    const float* Sp = &g_S[bz][it0 * 128][0];
    const float* vp = &g_v[h][b * BLK][0];
#pragma unroll
    for (int it = 0; it < 2; ++it) {
        int r = arow + it * 64, kk = ac4 * 4;
        float4 va = *(const float4*)(Sp + r * 256 + ac4 * 4);
        As[0][kk + 0][r] = va.x; As[0][kk + 1][r] = va.y;
        As[0][kk + 2][r] = va.z; As[0][kk + 3][r] = va.w;
        float4 vb = *(const float4*)(vp + (brow + it * 8) * 128 + bc4 * 4);
        *(float4*)&Bs[0][brow + it * 8][bc4 * 4] = vb;
    }
    __syncthreads();
    for (int t = 0; t < 16; t++) {
        const int cur = t & 1;
        float4 ra[2], rb[2];
        if (t + 1 < 16) {
            int k0 = (t + 1) * 16;
#pragma unroll
            for (int it = 0; it < 2; ++it) {
                ra[it] = *(const float4*)(Sp + (arow + it * 64) * 256 + k0 + ac4 * 4);
                rb[it] = *(const float4*)(vp + (k0 + brow + it * 8) * 128 + bc4 * 4);
            }
        }
        mm_tile16(&As[cur][0][0], &Bs[cur][0][0], tx, ty, c2);
        if (t + 1 < 16) {
            const int nx = cur ^ 1;
#pragma unroll
            for (int it = 0; it < 2; ++it) {
                int r = arow + it * 64, kk = ac4 * 4;
                As[nx][kk + 0][r] = ra[it].x; As[nx][kk + 1][r] = ra[it].y;
                As[nx][kk + 2][r] = ra[it].z; As[nx][kk + 3][r] = ra[it].w;
                *(float4*)&Bs[nx][brow + it * 8][bc4 * 4] = rb[it];
            }
        }
        __syncthreads();
    }

    const float* qp = &g_q[h][b * BLK + it0 * 128][0];
    const float* kvp = &g_kvin[h][b][0][0];
#pragma unroll
    for (int it = 0; it < 2; ++it) {
        int r = arow + it * 64, kk = ac4 * 4;
        float qd = __expf(-s * (float)(it0 * 128 + r + 1));
        float4 va = *(const float4*)(qp + r * 128 + ac4 * 4);
        As[0][kk + 0][r] = va.x * qd; As[0][kk + 1][r] = va.y * qd;
        As[0][kk + 2][r] = va.z * qd; As[0][kk + 3][r] = va.w * qd;
        float4 vb = *(const float4*)(kvp + (brow + it * 8) * 128 + bc4 * 4);
        *(float4*)&Bs[0][brow + it * 8][bc4 * 4] = vb;
    }
    __syncthreads();
    for (int t = 0; t < 8; t++) {
        const int cur = t & 1;
        float4 ra[2], rb[2];
        float qd2[2];
        if (t + 1 < 8) {
            int k0 = (t + 1) * 16;
#pragma unroll
            for (int it = 0; it < 2; ++it) {
                int r = arow + it * 64;
                qd2[it] = __expf(-s * (float)(it0 * 128 + r + 1));
                ra[it] = *(const float4*)(qp + r * 128 + k0 + ac4 * 4);
                rb[it] = *(const float4*)(kvp + (k0 + brow + it * 8) * 128 + bc4 * 4);
            }
        }
        mm_tile16(&As[cur][0][0], &Bs[cur][0][0], tx, ty, c2);
        if (t + 1 < 8) {
            const int nx = cur ^ 1;
#pragma unroll
            for (int it = 0; it < 2; ++it) {
                int r = arow + it * 64, kk = ac4 * 4;
                As[nx][kk + 0][r] = ra[it].x * qd2[it];
                As[nx][kk + 1][r] = ra[it].y * qd2[it];
                As[nx][kk + 2][r] = ra[it].z * qd2[it];
                As[nx][kk + 3][r] = ra[it].w * qd2[it];
                *(float4*)&Bs[nx][brow + it * 8][bc4 * 4] = rb[it];
            }
        }
        __syncthreads();
    }

#pragma unroll
    for (int i = 0; i < 8; i++) {
        int rl = (i < 4) ? (ty * 4 + i) : (64 + ty * 4 + i - 4);
        int mseq = b * BLK + it0 * 128 + rl;
#pragma unroll
        for (int hf = 0; hf < 2; ++hf) {
            float2 f0 = unpack2(c2[i][hf * 2 + 0]);
            float2 f1 = unpack2(c2[i][hf * 2 + 1]);
            *(float4*)&g_hidden[mseq][h * 128 + tx * 4 + hf * 64] =
                make_float4(f0.x, f0.y, f1.x, f1.y);
        }
    }
}

// ---------------- rmsnorm * norm_weight * sigmoid(gate) ----------------
__global__ void norm_kernel(const float* __restrict__ nw) {
    const int m = blockIdx.x;
    const int tid = threadIdx.x;
    const float4* hp = (const float4*)&g_hidden[m][0];
    float4 vals[4];
    float ss = 0.f;
#pragma unroll
    for (int i = 0; i < 4; i++) {
        float4 v = hp[tid + i * 256];
        vals[i] = v;
        ss += v.x * v.x + v.y * v.y + v.z * v.z + v.w * v.w;
    }
    __shared__ float red[256];
    red[tid] = ss;
    __syncthreads();
    for (int s = 128; s > 0; s >>= 1) {
        if (tid < s) red[tid] += red[tid + s];
        __syncthreads();
    }
    float inv = rsqrtf(red[0] / 4096.f + 1e-5f);
#pragma unroll
    for (int i = 0; i < 4; i++) {
        int c = (tid + i * 256) * 4;
        float4 v = vals[i];
        float4 g = *(const float4*)&g_gate[m][c];
        float4 w = *(const float4*)&nw[c];
        float4 o;
        o.x = v.x * inv * w.x * g.x;
        o.y = v.y * inv * w.y * g.y;
        o.z = v.z * inv * w.z * g.z;
        o.w = v.w * inv * w.w * g.w;
        *(float4*)&g_hidden2[m][c] = o;
    }
}

// ---------------- launch ----------------
extern "C" void kernel_launch(void* const* d_in, const int* in_sizes, int n_in,
                              void* d_out, int out_size) {
    const float* hs    = (const float*)d_in[0];
    const float* kv0   = (const float*)d_in[2];
    const float* Wqkv  = (const float*)d_in[3];
    const float* Wgate = (const float*)d_in[4];
    const float* Wout  = (const float*)d_in[5];
    const float* nw    = (const float*)d_in[6];
    float* out = (float*)d_out;

    float *hid2;
    __nv_bfloat16 *ah1, *al1, *ah2, *al2, *bqh, *bql, *bgh, *bgl, *boh, *bol;
    cudaGetSymbolAddress((void**)&hid2, g_hidden2);
    cudaGetSymbolAddress((void**)&ah1, g_Ah1);
    cudaGetSymbolAddress((void**)&al1, g_Al1);
    cudaGetSymbolAddress((void**)&ah2, g_Ah2);
    cudaGetSymbolAddress((void**)&al2, g_Al2);
    cudaGetSymbolAddress((void**)&bqh, g_Bqh);
    cudaGetSymbolAddress((void**)&bql, g_Bql);
    cudaGetSymbolAddress((void**)&bgh, g_Bgh);
    cudaGetSymbolAddress((void**)&bgl, g_Bgl);
    cudaGetSymbolAddress((void**)&boh, g_Boh);
    cudaGetSymbolAddress((void**)&bol, g_Bol);

    cudaFuncSetAttribute(gemm_mma_kernel<0>, cudaFuncAttributeMaxDynamicSharedMemorySize, SMEM_GEMM);
    cudaFuncSetAttribute(gemm_mma_kernel<1>, cudaFuncAttributeMaxDynamicSharedMemorySize, SMEM_GEMM);
    cudaFuncSetAttribute(gemm_mma_kernel<2>, cudaFuncAttributeMaxDynamicSharedMemorySize, SMEM_GEMM);

    dim3 thr(256);
    // operand conversions (fp32 -> bf16 hi/lo, tiled & pre-swizzled)
    conv_a_kernel<<<dim3(32, 32), thr>>>(hs, ah1, al1, HIDDIM);
    conv_w_kernel<<<dim3(32, 96), thr>>>(Wqkv, bqh, bql, 3 * INNERD);
    conv_w_kernel<<<dim3(32, 32), thr>>>(Wgate, bgh, bgl, INNERD);
    conv_w_kernel<<<dim3(64, 16), thr>>>(Wout, boh, bol, HIDDIM);

    // qkv = silu(hs @ W_qkv) -> scatter q/k/v    (M=4096, N=12288, K=2048)
    gemm_mma_kernel<2><<<dim3(32, 48), thr, SMEM_GEMM>>>(ah1, al1, bqh, bql, nullptr, 32, 3 * INNERD);
    // gate = sigmoid(hs @ W_gate)                (N=4096)
    gemm_mma_kernel<1><<<dim3(32, 16), thr, SMEM_GEMM>>>(ah1, al1, bgh, bgl, nullptr, 32, INNERD);

    // attention
    kvblock_kernel<<<dim3(NBK, HN), thr>>>();
    scan_kernel<<<2048, thr>>>(kv0);
    qk_kernel<<<dim3(2, 2, HN * NBK), thr>>>();
    av_kernel<<<dim3(2, HN * NBK), thr>>>();

    // rmsnorm * w * gate
    norm_kernel<<<NSEQ, thr>>>(nw);

    // out = hidden2 @ W_out                      (M=4096, N=2048, K=4096)
    conv_a_kernel<<<dim3(64, 32), thr>>>(hid2, ah2, al2, INNERD);
    gemm_mma_kernel<0><<<dim3(32, 8), thr, SMEM_GEMM>>>(ah2, al2, boh, bol, out, 64, HIDDIM);
}